// round 1
// baseline (speedup 1.0000x reference)
#include <cuda_runtime.h>
#include <math.h>

#define NE 64
#define NUP 32
#define NN 16
#define FD 8
#define DD 128
#define NL 3
#define NB 512
#define NTHREADS 512

// Global scratch (allowed: __device__ globals). 
// g_H[l] = G[l] @ W3[l], the folded z_n->output path (layer-invariant x0 multiplies it).
__device__ float g_H[NL][DD][DD];
// ee RBF features, diag-masked, computed once per batch element (layer-invariant).
__device__ float g_feat[NB][NE][NE][FD];

__device__ __forceinline__ void fma4(float4& acc, float s, const float4& v) {
    acc.x = fmaf(s, v.x, acc.x);
    acc.y = fmaf(s, v.y, acc.y);
    acc.z = fmaf(s, v.z, acc.z);
    acc.w = fmaf(s, v.w, acc.w);
}
__device__ __forceinline__ void fma4v(float4& acc, const float4& a, const float4& b) {
    acc.x = fmaf(a.x, b.x, acc.x);
    acc.y = fmaf(a.y, b.y, acc.y);
    acc.z = fmaf(a.z, b.z, acc.z);
    acc.w = fmaf(a.w, b.w, acc.w);
}

// ---------------------------------------------------------------------------
// Prepass: H[l][k][e] = sum_d we_ne[l,f,d] * y[n,d] * w_up[l, 384+d, e],  k = n*8+f
// ---------------------------------------------------------------------------
__global__ void prep_H_kernel(const float* __restrict__ embed_table,
                              const int*   __restrict__ atom_types,
                              const float* __restrict__ we_ne,
                              const float* __restrict__ w_up)
{
    int l = blockIdx.y;
    int k = blockIdx.x;            // 0..127
    int n = k >> 3, f = k & 7;
    int e = threadIdx.x;           // 0..127
    const float* y  = embed_table + atom_types[n] * DD;
    const float* wn = we_ne + (l * FD + f) * DD;
    const float* w3 = w_up  + ((size_t)l * 4 * DD + 3 * DD) * DD;  // rows 384..511
    float acc = 0.f;
    #pragma unroll 4
    for (int d = 0; d < DD; d++)
        acc = fmaf(wn[d] * y[d], w3[(size_t)d * DD + e], acc);
    g_H[l][k][e] = acc;
}

// ---------------------------------------------------------------------------
// Main kernel: one CTA per batch element, runs all 3 layers in shared memory.
// ---------------------------------------------------------------------------
__global__ void __launch_bounds__(NTHREADS) gnn_kernel(
    const float* __restrict__ r,
    const float* __restrict__ Rn,
    const float* __restrict__ we_same,
    const float* __restrict__ we_anti,
    const float* __restrict__ w_up,
    const float* __restrict__ b_up,
    float* __restrict__ out)
{
    extern __shared__ float sm[];
    float* sx  = sm;                 // [64][128] current x
    float* sx0 = sx  + NE * DD;      // [64][128] initial x (for H term)
    float* szs = sx0 + NE * DD;      // [64][128] z_same
    float* sza = szs + NE * DD;      // [64][128] z_anti
    float* sws = sza + NE * DD;      // [8][128]  we_same[l]
    float* swa = sws + FD * DD;      // [8][128]  we_anti[l]
    float* sb  = swa + FD * DD;      // [128]     b_up[l]
    float* sr  = sb  + DD;           // [64][4]   electron positions

    const int b    = blockIdx.x;
    const int tid  = threadIdx.x;
    const int w    = tid >> 5;       // 16 warps
    const int lane = tid & 31;

    const float DEL = 4.0f / 7.0f;   // mu spacing of linspace(0,4,8)
    float S[7];
    #pragma unroll
    for (int k2 = 0; k2 < 7; k2++) S[k2] = expf(-DEL * DEL * (float)(2 * k2 + 1));

    // ---- load electron positions ----
    if (tid < NE * 3) {
        int i = tid / 3, c = tid % 3;
        sr[i * 4 + c] = r[((size_t)b * NE + i) * 3 + c];
    }
    __syncthreads();

    // ---- initial embeddings: x0[i][n*8+f] = RBF(|r_i - R_n|) ----
    for (int p = tid; p < NE * NN; p += NTHREADS) {
        int i = p >> 4, n = p & 15;
        float dx = sr[i * 4 + 0] - Rn[((size_t)b * NN + n) * 3 + 0];
        float dy = sr[i * 4 + 1] - Rn[((size_t)b * NN + n) * 3 + 1];
        float dz = sr[i * 4 + 2] - Rn[((size_t)b * NN + n) * 3 + 2];
        float d2   = fmaf(dx, dx, fmaf(dy, dy, dz * dz)) + 1e-12f;
        float dist = sqrtf(d2);
        float ft = __expf(-d2);                 // f = 0 term (mu_0 = 0)
        float q  = __expf(2.f * DEL * dist);
        #pragma unroll
        for (int f = 0; f < FD; f++) {
            sx0[i * DD + n * FD + f] = ft;
            sx [i * DD + n * FD + f] = ft;
            if (f < 7) ft = ft * q * S[f];
        }
    }

    // ---- ee RBF features (layer-invariant), diagonal masked to 0 ----
    float* gf = &g_feat[b][0][0][0];
    for (int p = tid; p < NE * NE; p += NTHREADS) {
        int i = p >> 6, j = p & 63;
        float dx = sr[i * 4 + 0] - sr[j * 4 + 0];
        float dy = sr[i * 4 + 1] - sr[j * 4 + 1];
        float dz = sr[i * 4 + 2] - sr[j * 4 + 2];
        float d2   = fmaf(dx, dx, fmaf(dy, dy, dz * dz)) + 1e-12f;
        float dist = sqrtf(d2);
        float msk = (i == j) ? 0.f : 1.f;
        float ft = msk * __expf(-d2);
        float q  = __expf(2.f * DEL * dist);
        float v[8];
        #pragma unroll
        for (int f = 0; f < FD; f++) { v[f] = ft; if (f < 7) ft = ft * q * S[f]; }
        float4* dst = (float4*)(gf + (size_t)p * 8);
        dst[0] = make_float4(v[0], v[1], v[2], v[3]);
        dst[1] = make_float4(v[4], v[5], v[6], v[7]);
    }
    __syncthreads();

    // ---- 3 message-passing layers ----
    for (int l = 0; l < NL; l++) {
        // stage per-layer edge weights + bias
        for (int t = tid; t < FD * DD; t += NTHREADS) {
            sws[t] = we_same[(size_t)l * FD * DD + t];
            swa[t] = we_anti[(size_t)l * FD * DD + t];
        }
        if (tid < DD) sb[tid] = b_up[(size_t)l * DD + tid];
        __syncthreads();

        // ===== message phase: z_s[i,:], z_a[i,:]; warp w owns electrons w*4..w*4+3,
        //       lane owns d = lane*4..lane*4+3 =====
        #pragma unroll 1
        for (int ii = 0; ii < 4; ii++) {
            int  i   = w * 4 + ii;
            int  iup = (i < NUP) ? 1 : 0;
            #pragma unroll 1
            for (int pass = 0; pass < 2; pass++) {
                // pass 0 = same-spin 32-group, pass 1 = anti-spin 32-group
                int jbase = (((pass == 0) ? 1 : 0) == iup) ? 0 : NUP;
                float4 t[8];
                #pragma unroll
                for (int f = 0; f < 8; f++) t[f] = make_float4(0.f, 0.f, 0.f, 0.f);

                const float* fbase = gf + ((size_t)i * NE + jbase) * 8;
                const float* xbase = sx + (size_t)jbase * DD + lane * 4;
                #pragma unroll 4
                for (int jj = 0; jj < NUP; jj++) {
                    float4 flo = *(const float4*)(fbase + (size_t)jj * 8);
                    float4 fhi = *(const float4*)(fbase + (size_t)jj * 8 + 4);
                    float4 xj  = *(const float4*)(xbase + (size_t)jj * DD);
                    fma4(t[0], flo.x, xj); fma4(t[1], flo.y, xj);
                    fma4(t[2], flo.z, xj); fma4(t[3], flo.w, xj);
                    fma4(t[4], fhi.x, xj); fma4(t[5], fhi.y, xj);
                    fma4(t[6], fhi.z, xj); fma4(t[7], fhi.w, xj);
                }
                // reduce over f with we_same/we_anti
                const float* wp = (pass == 0) ? sws : swa;
                float4 z = make_float4(0.f, 0.f, 0.f, 0.f);
                #pragma unroll
                for (int f = 0; f < 8; f++) {
                    float4 wf = *(const float4*)(wp + f * DD + lane * 4);
                    fma4v(z, t[f], wf);
                }
                float* zdst = ((pass == 0) ? szs : sza) + (size_t)i * DD + lane * 4;
                *(float4*)zdst = z;
            }
        }
        __syncthreads();

        // ===== update phase: pre = x@W0 + z_s@W1 + z_a@W2 + x0@H[l] =====
        float4 acc[4];
        #pragma unroll
        for (int ii = 0; ii < 4; ii++) acc[ii] = make_float4(0.f, 0.f, 0.f, 0.f);

        const float* Wl = w_up + (size_t)l * 4 * DD * DD;
        #pragma unroll 1
        for (int src = 0; src < 4; src++) {
            const float* A  = (src == 0) ? sx : (src == 1) ? szs : (src == 2) ? sza : sx0;
            const float* Bm = (src < 3) ? (Wl + (size_t)src * DD * DD) : &g_H[l][0][0];
            #pragma unroll 1
            for (int k4 = 0; k4 < DD; k4 += 4) {
                float4 w0 = *(const float4*)(Bm + (size_t)(k4 + 0) * DD + lane * 4);
                float4 w1 = *(const float4*)(Bm + (size_t)(k4 + 1) * DD + lane * 4);
                float4 w2 = *(const float4*)(Bm + (size_t)(k4 + 2) * DD + lane * 4);
                float4 w3 = *(const float4*)(Bm + (size_t)(k4 + 3) * DD + lane * 4);
                #pragma unroll
                for (int ii = 0; ii < 4; ii++) {
                    float4 a = *(const float4*)(A + (size_t)(w * 4 + ii) * DD + k4);
                    fma4(acc[ii], a.x, w0);
                    fma4(acc[ii], a.y, w1);
                    fma4(acc[ii], a.z, w2);
                    fma4(acc[ii], a.w, w3);
                }
            }
        }
        __syncthreads();   // all reads of sx/szs/sza done before sx overwrite

        float4 bb = *(const float4*)(sb + lane * 4);
        #pragma unroll
        for (int ii = 0; ii < 4; ii++) {
            int i = w * 4 + ii;
            float4 xo = *(const float4*)(sx + (size_t)i * DD + lane * 4);
            float4 v;
            v.x = xo.x + tanhf(acc[ii].x + bb.x);
            v.y = xo.y + tanhf(acc[ii].y + bb.y);
            v.z = xo.z + tanhf(acc[ii].z + bb.z);
            v.w = xo.w + tanhf(acc[ii].w + bb.w);
            *(float4*)(sx + (size_t)i * DD + lane * 4) = v;
        }
        __syncthreads();
    }

    // ---- write result ----
    const float4* s4 = (const float4*)sx;
    float4* o4 = (float4*)(out + (size_t)b * NE * DD);
    for (int t = tid; t < NE * DD / 4; t += NTHREADS) o4[t] = s4[t];
}

// ---------------------------------------------------------------------------
// Launch
// ---------------------------------------------------------------------------
extern "C" void kernel_launch(void* const* d_in, const int* in_sizes, int n_in,
                              void* d_out, int out_size)
{
    const float* r  = (const float*)d_in[0];   // [512,64,3]
    const float* Rn = (const float*)d_in[1];   // [512,16,3]
    const float* et = (const float*)d_in[2];   // [4,128]
    const float* ws = (const float*)d_in[3];   // [3,8,128]
    const float* wa = (const float*)d_in[4];   // [3,8,128]
    const float* wn = (const float*)d_in[5];   // [3,8,128]
    const float* wu = (const float*)d_in[6];   // [3,512,128]
    const float* bu = (const float*)d_in[7];   // [3,128]
    const int*   at = (const int*)d_in[8];     // [16]
    float* out = (float*)d_out;                // [512,64,128]

    const int smem_bytes = (4 * NE * DD + 2 * FD * DD + DD + NE * 4) * (int)sizeof(float); // 140800
    cudaFuncSetAttribute(gnn_kernel, cudaFuncAttributeMaxDynamicSharedMemorySize, smem_bytes);

    prep_H_kernel<<<dim3(DD, NL), DD>>>(et, at, wn, wu);
    gnn_kernel<<<NB, NTHREADS, smem_bytes>>>(r, Rn, ws, wa, wu, bu, out);
}

// round 2
// speedup vs baseline: 1.0332x; 1.0332x over previous
#include <cuda_runtime.h>
#include <math.h>

#define NE 64
#define NUP 32
#define NN 16
#define FD 8
#define DD 128
#define NL 3
#define NB 512
#define NTHREADS 512

typedef unsigned long long u64;

// Global scratch.
__device__ float g_H[NL][DD][DD];                 // folded z_n path: G[l] @ W3[l]
__device__ float g_feat[NB][NE][NE][FD];          // ee RBF features (layer-invariant)

// ---- packed fp32x2 helpers (Blackwell FFMA2 path) ----
__device__ __forceinline__ u64 pk2(float lo, float hi) {
    u64 r; asm("mov.b64 %0,{%1,%2};" : "=l"(r) : "f"(lo), "f"(hi)); return r;
}
__device__ __forceinline__ u64 pk1(float s) {
    u64 r; asm("mov.b64 %0,{%1,%1};" : "=l"(r) : "f"(s)); return r;
}
__device__ __forceinline__ void fm2(u64& d, u64 a, u64 b) {
    asm("fma.rn.f32x2 %0,%1,%2,%0;" : "+l"(d) : "l"(a), "l"(b));
}
__device__ __forceinline__ float2 up2(u64 v) {
    float2 r; asm("mov.b64 {%0,%1},%2;" : "=f"(r.x), "=f"(r.y) : "l"(v)); return r;
}

// ---------------------------------------------------------------------------
// Prepass: H[l][k][e] = sum_d we_ne[l,f,d]*y[n,d]*w_up[l,384+d,e],  k = n*8+f
// ---------------------------------------------------------------------------
__global__ void prep_H_kernel(const float* __restrict__ embed_table,
                              const int*   __restrict__ atom_types,
                              const float* __restrict__ we_ne,
                              const float* __restrict__ w_up)
{
    int l = blockIdx.y;
    int k = blockIdx.x;
    int n = k >> 3, f = k & 7;
    int e = threadIdx.x;
    const float* y  = embed_table + atom_types[n] * DD;
    const float* wn = we_ne + (l * FD + f) * DD;
    const float* w3 = w_up  + ((size_t)l * 4 * DD + 3 * DD) * DD;
    float acc = 0.f;
    #pragma unroll 4
    for (int d = 0; d < DD; d++)
        acc = fmaf(wn[d] * y[d], w3[(size_t)d * DD + e], acc);
    g_H[l][k][e] = acc;
}

// ---------------------------------------------------------------------------
// Main kernel: one CTA per batch element, 3 layers in shared memory, f32x2 math.
// ---------------------------------------------------------------------------
__global__ void __launch_bounds__(NTHREADS) gnn_kernel(
    const float* __restrict__ r,
    const float* __restrict__ Rn,
    const float* __restrict__ we_same,
    const float* __restrict__ we_anti,
    const float* __restrict__ w_up,
    const float* __restrict__ b_up,
    float* __restrict__ out)
{
    extern __shared__ float sm[];
    float* sx    = sm;                   // [64][128] current x
    float* sx0   = sx    + NE * DD;      // [64][128] initial x
    float* szs   = sx0   + NE * DD;      // [64][128] z_same
    float* sza   = szs   + NE * DD;      // [64][128] z_anti
    float* spart = sza   + NE * DD;      // [64][128] cross-half GEMM partials
    float* sws   = spart + NE * DD;      // [8][128]  we_same[l]
    float* swa   = sws   + FD * DD;      // [8][128]  we_anti[l]
    float* sb    = swa   + FD * DD;      // [128]     b_up[l]
    float* sr    = sb    + DD;           // [64][4]   electron positions

    const int b    = blockIdx.x;
    const int tid  = threadIdx.x;
    const int w    = tid >> 5;           // 16 warps
    const int lane = tid & 31;

    const float DEL = 4.0f / 7.0f;
    float S[7];
    #pragma unroll
    for (int k2 = 0; k2 < 7; k2++) S[k2] = expf(-DEL * DEL * (float)(2 * k2 + 1));

    // ---- electron positions ----
    if (tid < NE * 3) {
        int i = tid / 3, c = tid % 3;
        sr[i * 4 + c] = r[((size_t)b * NE + i) * 3 + c];
    }
    __syncthreads();

    // ---- initial embeddings x0 ----
    for (int p = tid; p < NE * NN; p += NTHREADS) {
        int i = p >> 4, n = p & 15;
        float dx = sr[i * 4 + 0] - Rn[((size_t)b * NN + n) * 3 + 0];
        float dy = sr[i * 4 + 1] - Rn[((size_t)b * NN + n) * 3 + 1];
        float dz = sr[i * 4 + 2] - Rn[((size_t)b * NN + n) * 3 + 2];
        float d2   = fmaf(dx, dx, fmaf(dy, dy, dz * dz)) + 1e-12f;
        float dist = sqrtf(d2);
        float ft = __expf(-d2);
        float q  = __expf(2.f * DEL * dist);
        #pragma unroll
        for (int f = 0; f < FD; f++) {
            sx0[i * DD + n * FD + f] = ft;
            sx [i * DD + n * FD + f] = ft;
            if (f < 7) ft = ft * q * S[f];
        }
    }

    // ---- ee RBF features (diag-masked) ----
    float* gf = &g_feat[b][0][0][0];
    for (int p = tid; p < NE * NE; p += NTHREADS) {
        int i = p >> 6, j = p & 63;
        float dx = sr[i * 4 + 0] - sr[j * 4 + 0];
        float dy = sr[i * 4 + 1] - sr[j * 4 + 1];
        float dz = sr[i * 4 + 2] - sr[j * 4 + 2];
        float d2   = fmaf(dx, dx, fmaf(dy, dy, dz * dz)) + 1e-12f;
        float dist = sqrtf(d2);
        float msk = (i == j) ? 0.f : 1.f;
        float ft = msk * __expf(-d2);
        float q  = __expf(2.f * DEL * dist);
        float v[8];
        #pragma unroll
        for (int f = 0; f < FD; f++) { v[f] = ft; if (f < 7) ft = ft * q * S[f]; }
        float4* dst = (float4*)(gf + (size_t)p * 8);
        dst[0] = make_float4(v[0], v[1], v[2], v[3]);
        dst[1] = make_float4(v[4], v[5], v[6], v[7]);
    }
    __syncthreads();

    // update-phase thread mapping (k-split across warp pairs)
    const int half  = w & 1;
    const int g     = w >> 1;            // 8 i-groups of 8
    const int dslot = lane & 15;
    const int ihalf = lane >> 4;
    const int i0    = g * 8 + ihalf * 4;
    const int d0    = dslot * 8;

    // ---- layers ----
    for (int l = 0; l < NL; l++) {
        for (int t = tid; t < FD * DD; t += NTHREADS) {
            sws[t] = we_same[(size_t)l * FD * DD + t];
            swa[t] = we_anti[(size_t)l * FD * DD + t];
        }
        if (tid < DD) sb[tid] = b_up[(size_t)l * DD + tid];
        __syncthreads();

        // ===== message phase: warp w owns electrons w*4..w*4+3, lane owns d=lane*4..+3
        //       f32x2 lanes = f-pairs =====
        #pragma unroll 1
        for (int pass = 0; pass < 2; pass++) {
            const float* wsrc = pass ? swa : sws;
            u64 wp[16];     // [fp][c] = {we[2fp][d], we[2fp+1][d]}
            #pragma unroll
            for (int fp = 0; fp < 4; fp++)
                #pragma unroll
                for (int c = 0; c < 4; c++)
                    wp[fp * 4 + c] = pk2(wsrc[(2 * fp) * DD + lane * 4 + c],
                                         wsrc[(2 * fp + 1) * DD + lane * 4 + c]);

            #pragma unroll 1
            for (int ii = 0; ii < 4; ii++) {
                int i   = w * 4 + ii;
                int iup = (i < NUP) ? 1 : 0;
                int jbase = (((pass == 0) ? 1 : 0) == iup) ? 0 : NUP;

                u64 t[16];  // [fp][c]
                #pragma unroll
                for (int q2 = 0; q2 < 16; q2++) t[q2] = 0ull;

                const float* fbase = gf + ((size_t)i * NE + jbase) * 8;
                const float* xbase = sx + (size_t)jbase * DD + lane * 4;
                #pragma unroll 4
                for (int jj = 0; jj < NUP; jj++) {
                    ulonglong2 fA = *(const ulonglong2*)(fbase + (size_t)jj * 8);
                    ulonglong2 fB = *(const ulonglong2*)(fbase + (size_t)jj * 8 + 4);
                    float4 xj = *(const float4*)(xbase + (size_t)jj * DD);
                    u64 x0p = pk1(xj.x), x1p = pk1(xj.y), x2p = pk1(xj.z), x3p = pk1(xj.w);
                    fm2(t[0],  fA.x, x0p); fm2(t[1],  fA.x, x1p);
                    fm2(t[2],  fA.x, x2p); fm2(t[3],  fA.x, x3p);
                    fm2(t[4],  fA.y, x0p); fm2(t[5],  fA.y, x1p);
                    fm2(t[6],  fA.y, x2p); fm2(t[7],  fA.y, x3p);
                    fm2(t[8],  fB.x, x0p); fm2(t[9],  fB.x, x1p);
                    fm2(t[10], fB.x, x2p); fm2(t[11], fB.x, x3p);
                    fm2(t[12], fB.y, x0p); fm2(t[13], fB.y, x1p);
                    fm2(t[14], fB.y, x2p); fm2(t[15], fB.y, x3p);
                }
                // reduce over f-pairs with we
                float zv[4];
                #pragma unroll
                for (int c = 0; c < 4; c++) {
                    u64 s = 0ull;
                    fm2(s, t[0 + c],  wp[0 + c]);
                    fm2(s, t[4 + c],  wp[4 + c]);
                    fm2(s, t[8 + c],  wp[8 + c]);
                    fm2(s, t[12 + c], wp[12 + c]);
                    float2 sv = up2(s);
                    zv[c] = sv.x + sv.y;
                }
                float* zdst = ((pass == 0) ? szs : sza) + (size_t)i * DD + lane * 4;
                *(float4*)zdst = make_float4(zv[0], zv[1], zv[2], zv[3]);
            }
        }
        __syncthreads();

        // ===== update phase: pre = x@W0 + zs@W1 + za@W2 + x0@H[l], K split by half =====
        u64 acc[16];    // [ii][dp]
        #pragma unroll
        for (int q2 = 0; q2 < 16; q2++) acc[q2] = 0ull;

        const float* Wl = w_up + (size_t)l * 4 * DD * DD;
        #pragma unroll 1
        for (int s2 = 0; s2 < 2; s2++) {
            int src = half * 2 + s2;
            const float* A  = (src == 0) ? sx : (src == 1) ? szs : (src == 2) ? sza : sx0;
            const float* Bm = (src < 3) ? (Wl + (size_t)src * DD * DD) : &g_H[l][0][0];
            #pragma unroll 1
            for (int k4 = 0; k4 < DD; k4 += 4) {
                float4 a4[4];
                #pragma unroll
                for (int ii = 0; ii < 4; ii++)
                    a4[ii] = *(const float4*)(A + (size_t)(i0 + ii) * DD + k4);
                #pragma unroll
                for (int kk = 0; kk < 4; kk++) {
                    const float* wr = Bm + (size_t)(k4 + kk) * DD + d0;
                    ulonglong2 wA = *(const ulonglong2*)(wr);
                    ulonglong2 wB = *(const ulonglong2*)(wr + 4);
                    #pragma unroll
                    for (int ii = 0; ii < 4; ii++) {
                        float av = (kk == 0) ? a4[ii].x : (kk == 1) ? a4[ii].y
                                 : (kk == 2) ? a4[ii].z : a4[ii].w;
                        u64 ap = pk1(av);
                        fm2(acc[ii * 4 + 0], ap, wA.x);
                        fm2(acc[ii * 4 + 1], ap, wA.y);
                        fm2(acc[ii * 4 + 2], ap, wB.x);
                        fm2(acc[ii * 4 + 3], ap, wB.y);
                    }
                }
            }
        }

        // exchange: half h writes the d-pairs the OTHER half finalizes
        {
            int wdp  = (half == 0) ? 2 : 0;
            int woff = (half == 0) ? 4 : 0;
            #pragma unroll
            for (int ii = 0; ii < 4; ii++) {
                u64* dst = (u64*)(spart + (size_t)(i0 + ii) * DD + d0 + woff);
                dst[0] = acc[ii * 4 + wdp];
                dst[1] = acc[ii * 4 + wdp + 1];
            }
        }
        __syncthreads();

        // finalize own d-half: pre = own partial + other's partial + b; x += tanh(pre)
        {
            int fdp = (half == 0) ? 0 : 2;
            int fd  = d0 + ((half == 0) ? 0 : 4);
            float2 b01 = *(const float2*)(sb + fd);
            float2 b23 = *(const float2*)(sb + fd + 2);
            #pragma unroll
            for (int ii = 0; ii < 4; ii++) {
                int i = i0 + ii;
                const u64* par = (const u64*)(spart + (size_t)i * DD + fd);
                float2 p0 = up2(par[0]), p1 = up2(par[1]);
                float2 m0 = up2(acc[ii * 4 + fdp]), m1 = up2(acc[ii * 4 + fdp + 1]);
                float* xr = sx + (size_t)i * DD + fd;
                float4 xo = *(const float4*)xr;
                float4 v;
                v.x = xo.x + tanhf(m0.x + p0.x + b01.x);
                v.y = xo.y + tanhf(m0.y + p0.y + b01.y);
                v.z = xo.z + tanhf(m1.x + p1.x + b23.x);
                v.w = xo.w + tanhf(m1.y + p1.y + b23.y);
                *(float4*)xr = v;
            }
        }
        __syncthreads();
    }

    // ---- write result ----
    const float4* s4 = (const float4*)sx;
    float4* o4 = (float4*)(out + (size_t)b * NE * DD);
    for (int t = tid; t < NE * DD / 4; t += NTHREADS) o4[t] = s4[t];
}

// ---------------------------------------------------------------------------
// Launch
// ---------------------------------------------------------------------------
extern "C" void kernel_launch(void* const* d_in, const int* in_sizes, int n_in,
                              void* d_out, int out_size)
{
    const float* r  = (const float*)d_in[0];
    const float* Rn = (const float*)d_in[1];
    const float* et = (const float*)d_in[2];
    const float* ws = (const float*)d_in[3];
    const float* wa = (const float*)d_in[4];
    const float* wn = (const float*)d_in[5];
    const float* wu = (const float*)d_in[6];
    const float* bu = (const float*)d_in[7];
    const int*   at = (const int*)d_in[8];
    float* out = (float*)d_out;

    const int smem_bytes = (5 * NE * DD + 2 * FD * DD + DD + NE * 4) * (int)sizeof(float);
    cudaFuncSetAttribute(gnn_kernel, cudaFuncAttributeMaxDynamicSharedMemorySize, smem_bytes);

    prep_H_kernel<<<dim3(DD, NL), DD>>>(et, at, wn, wu);
    gnn_kernel<<<NB, NTHREADS, smem_bytes>>>(r, Rn, ws, wa, wu, bu, out);
}